// round 7
// baseline (speedup 1.0000x reference)
#include <cuda_runtime.h>
#include <math.h>
#include <stdint.h>

#define T_TOK 8192
#define D_DIM 1024
#define H_DIM 2048
#define E_NUM 8
#define NA (T_TOK * 2)

// ---------------- scratch (device globals; no allocation) ----------------
__device__ int   g_cnt[E_NUM];
__device__ int   g_off[E_NUM];
__device__ int   g_cur[E_NUM];
__device__ int   g_sel[NA];
__device__ float g_prob[NA];
__device__ int   g_rows[NA];
__device__ int   g_tokpos[NA];
__device__ float g_xc[(size_t)T_TOK * D_DIM];                //  32 MB tf32 x
__device__ float g_h [(size_t)NA * H_DIM];                   // 128 MB silu product (tf32)
__device__ float g_y [(size_t)NA * D_DIM];                   //  64 MB expert outputs
__device__ float g_w1T[(size_t)E_NUM * H_DIM * D_DIM];       //  64 MB [e][h][d] tf32
__device__ float g_w3T[(size_t)E_NUM * H_DIM * D_DIM];       //  64 MB [e][h][d] tf32
__device__ float g_w2T[(size_t)E_NUM * D_DIM * H_DIM];       //  64 MB [e][d][h] tf32

// ================= helpers =================
__device__ __forceinline__ uint32_t smem_u32(const void* p) {
    uint32_t a;
    asm("{ .reg .u64 t; cvta.to.shared.u64 t, %1; cvt.u32.u64 %0, t; }" : "=r"(a) : "l"(p));
    return a;
}
__device__ __forceinline__ uint32_t f2tf32(float x) {
    uint32_t u;
    asm("cvt.rna.tf32.f32 %0, %1;" : "=r"(u) : "f"(x));
    return u;
}

#define CP_ASYNC16(dst, src) \
    asm volatile("cp.async.cg.shared.global [%0], [%1], 16;" :: "r"(dst), "l"(src) : "memory")
#define CP_COMMIT() asm volatile("cp.async.commit_group;" ::: "memory")
#define CP_WAIT2()  asm volatile("cp.async.wait_group 2;" ::: "memory")

#define LDSM_X4(r, addr) \
    asm volatile("ldmatrix.sync.aligned.m8n8.x4.shared.b16 {%0,%1,%2,%3}, [%4];" \
        : "=r"((r)[0]), "=r"((r)[1]), "=r"((r)[2]), "=r"((r)[3]) : "r"(addr))
#define LDSM_X2(r, addr) \
    asm volatile("ldmatrix.sync.aligned.m8n8.x2.shared.b16 {%0,%1}, [%2];" \
        : "=r"((r)[0]), "=r"((r)[1]) : "r"(addr))

#define MMA_TF32(d, a, b) \
    asm volatile("mma.sync.aligned.m16n8k8.row.col.f32.tf32.tf32.f32 " \
        "{%0,%1,%2,%3}, {%4,%5,%6,%7}, {%8,%9}, {%0,%1,%2,%3};" \
        : "+f"((d)[0]), "+f"((d)[1]), "+f"((d)[2]), "+f"((d)[3]) \
        : "r"((a)[0]), "r"((a)[1]), "r"((a)[2]), "r"((a)[3]), "r"((b)[0]), "r"((b)[1]))

// ---------------- init ----------------
__global__ void init_kernel() {
    int i = threadIdx.x;
    if (i < E_NUM) { g_cnt[i] = 0; g_cur[i] = 0; }
}

// ---------------- x -> tf32 copy ----------------
__global__ void cvt_x_kernel(const float* __restrict__ x) {
    size_t i = ((size_t)blockIdx.x * blockDim.x + threadIdx.x) * 4;
    float4 v = *reinterpret_cast<const float4*>(x + i);
    uint4 o;
    o.x = f2tf32(v.x); o.y = f2tf32(v.y); o.z = f2tf32(v.z); o.w = f2tf32(v.w);
    *reinterpret_cast<uint4*>(g_xc + i) = o;
}

// ---------------- weight transpose + tf32 round: [E][R][C] -> [E][C][R] ----------------
__global__ void transpose_cvt_kernel(const float* __restrict__ src, float* __restrict__ dst,
                                     int R, int C) {
    __shared__ float tile[32][33];
    size_t eoff = (size_t)blockIdx.z * R * C;
    src += eoff; dst += eoff;
    int c0 = blockIdx.x * 32, r0 = blockIdx.y * 32;
    int tx = threadIdx.x, ty = threadIdx.y;
#pragma unroll
    for (int i = 0; i < 4; i++)
        tile[ty + i * 8][tx] = src[(size_t)(r0 + ty + i * 8) * C + c0 + tx];
    __syncthreads();
#pragma unroll
    for (int i = 0; i < 4; i++)
        dst[(size_t)(c0 + ty + i * 8) * R + r0 + tx] =
            __uint_as_float(f2tf32(tile[tx][ty + i * 8]));
}

// ---------------- gating: warp per token (exact fp32) ----------------
__global__ void gate_kernel(const float* __restrict__ x, const float* __restrict__ wg) {
    int warp = (blockIdx.x * blockDim.x + threadIdx.x) >> 5;
    int lane = threadIdx.x & 31;
    if (warp >= T_TOK) return;
    const float* xr = x + (size_t)warp * D_DIM;
    float acc[E_NUM];
#pragma unroll
    for (int e = 0; e < E_NUM; e++) acc[e] = 0.f;
    for (int d = lane; d < D_DIM; d += 32) {
        float xv = xr[d];
        const float* w = wg + (size_t)d * E_NUM;
#pragma unroll
        for (int e = 0; e < E_NUM; e++) acc[e] += xv * w[e];
    }
#pragma unroll
    for (int e = 0; e < E_NUM; e++) {
#pragma unroll
        for (int o = 16; o > 0; o >>= 1)
            acc[e] += __shfl_xor_sync(0xffffffff, acc[e], o);
    }
    if (lane == 0) {
        float best = -1e30f, sec = -1e30f;
        int bi = 0, si = 0;
#pragma unroll
        for (int e = 0; e < E_NUM; e++) {
            float v = acc[e];
            if (v > best) { sec = best; si = bi; best = v; bi = e; }
            else if (v > sec) { sec = v; si = e; }
        }
        float p0 = 1.f / (1.f + expf(sec - best));
        g_sel[warp * 2]      = bi;
        g_sel[warp * 2 + 1]  = si;
        g_prob[warp * 2]     = p0;
        g_prob[warp * 2 + 1] = 1.f - p0;
        atomicAdd(&g_cnt[bi], 1);
        atomicAdd(&g_cnt[si], 1);
    }
}

__global__ void offsets_kernel() {
    if (threadIdx.x == 0) {
        int r = 0;
        for (int e = 0; e < E_NUM; e++) { g_off[e] = r; g_cur[e] = r; r += g_cnt[e]; }
    }
}

__global__ void scatter_kernel() {
    int t = blockIdx.x * blockDim.x + threadIdx.x;
    if (t >= T_TOK) return;
#pragma unroll
    for (int k = 0; k < 2; k++) {
        int e = g_sel[t * 2 + k];
        int pos = atomicAdd(&g_cur[e], 1);
        g_rows[pos]         = t;
        g_tokpos[t * 2 + k] = pos;
    }
}

// ================= GEMM1 fused: h = silu(Xg@W1) * (Xg@W3) =================
// CTA tile M=128, N=128 against BOTH W1 and W3. 8 warps (2m x 4n), warp tile 64x32
// per matrix, m16n8k8 tf32. 4-stage cp.async pipeline; stage = A(16K)+B1(16K)+B3(16K).
#define G1_STAGE 49152
#define G1_SMEM  (4 * G1_STAGE)
__global__ __launch_bounds__(256, 1) void gemm1_fused(const float* __restrict__ Abase) {
    const int NT = D_DIM / 32;      // 32 k-tiles
    int e  = blockIdx.y;
    int Me = g_cnt[e];
    int m0 = blockIdx.x * 128;
    if (m0 >= Me) return;
    int n0   = blockIdx.z * 128;
    int base = g_off[e];
    const float* B1m = g_w1T + (size_t)e * H_DIM * D_DIM;
    const float* B3m = g_w3T + (size_t)e * H_DIM * D_DIM;

    extern __shared__ char ds[];
    uint32_t sb = smem_u32(ds);
    int tid = threadIdx.x, lane = tid & 31, wid = tid >> 5;
    int wm = wid & 1, wn = wid >> 1;

    // loader: A, B1, B3 each 128 rows x 32k -> 4 float4 per thread each
    const float* aSrc[4];  uint32_t aDst[4];
    const float* b1Src[4]; const float* b3Src[4]; uint32_t bDst[4];
#pragma unroll
    for (int j = 0; j < 4; j++) {
        int v = tid + j * 256, q = v & 7, m = v >> 3;
        int mg = m0 + m; if (mg > Me - 1) mg = Me - 1;
        aSrc[j]  = Abase + (size_t)g_rows[base + mg] * D_DIM + q * 4;
        b1Src[j] = B1m + (size_t)(n0 + m) * D_DIM + q * 4;
        b3Src[j] = B3m + (size_t)(n0 + m) * D_DIM + q * 4;
        uint32_t off = (uint32_t)(m * 128) + (uint32_t)((q ^ (m & 7)) << 4);
        aDst[j] = sb + off;
        bDst[j] = sb + 16384u + off;
    }

    float acc1[4][4][4], acc3[4][4][4];
#pragma unroll
    for (int mf = 0; mf < 4; mf++)
#pragma unroll
        for (int nf = 0; nf < 4; nf++)
#pragma unroll
            for (int r = 0; r < 4; r++) { acc1[mf][nf][r] = 0.f; acc3[mf][nf][r] = 0.f; }

    // prologue: stages 0..2
#pragma unroll
    for (int s = 0; s < 3; s++) {
        uint32_t bo = (uint32_t)s * G1_STAGE;
        int kof = s * 32;
#pragma unroll
        for (int j = 0; j < 4; j++) {
            CP_ASYNC16(aDst[j] + bo,          aSrc[j]  + kof);
            CP_ASYNC16(bDst[j] + bo,          b1Src[j] + kof);
            CP_ASYNC16(bDst[j] + bo + 16384u, b3Src[j] + kof);
        }
        CP_COMMIT();
    }

    int arow[4];
#pragma unroll
    for (int mf = 0; mf < 4; mf++)
        arow[mf] = wm * 64 + mf * 16 + (lane & 7) + ((lane >> 3) & 1) * 8;
    int aci = lane >> 4;
    int brow[4];
#pragma unroll
    for (int nf = 0; nf < 4; nf++)
        brow[nf] = wn * 32 + nf * 8 + (lane & 7);
    int bci = (lane >> 3) & 1;

    for (int t = 0; t < NT; t++) {
        CP_WAIT2();                 // stage t complete
        __syncthreads();            // all warps done with buffer being overwritten next
        int ls = t + 3;
        if (ls < NT) {
            uint32_t bo = (uint32_t)(ls & 3) * G1_STAGE;
            int kof = ls * 32;
#pragma unroll
            for (int j = 0; j < 4; j++) {
                CP_ASYNC16(aDst[j] + bo,          aSrc[j]  + kof);
                CP_ASYNC16(bDst[j] + bo,          b1Src[j] + kof);
                CP_ASYNC16(bDst[j] + bo + 16384u, b3Src[j] + kof);
            }
        }
        CP_COMMIT();

        uint32_t As  = sb + (uint32_t)(t & 3) * G1_STAGE;
        uint32_t B1s = As + 16384u;
        uint32_t B3s = As + 32768u;
#pragma unroll
        for (int ks = 0; ks < 4; ks++) {
            uint32_t a[4][4];
#pragma unroll
            for (int mf = 0; mf < 4; mf++) {
                uint32_t ad = As + (uint32_t)(arow[mf] * 128)
                            + (uint32_t)((((2 * ks + aci) ^ (arow[mf] & 7))) << 4);
                LDSM_X4(a[mf], ad);
            }
            uint32_t b1[4][2], b3[4][2];
#pragma unroll
            for (int nf = 0; nf < 4; nf++) {
                uint32_t co = (uint32_t)((((2 * ks + bci) ^ (brow[nf] & 7))) << 4);
                uint32_t ro = (uint32_t)(brow[nf] * 128);
                LDSM_X2(b1[nf], B1s + ro + co);
                LDSM_X2(b3[nf], B3s + ro + co);
            }
#pragma unroll
            for (int mf = 0; mf < 4; mf++)
#pragma unroll
                for (int nf = 0; nf < 4; nf++) {
                    MMA_TF32(acc1[mf][nf], a[mf], b1[nf]);
                    MMA_TF32(acc3[mf][nf], a[mf], b3[nf]);
                }
        }
    }

    // epilogue: silu(t1)*t3 -> g_h (tf32)
#pragma unroll
    for (int mf = 0; mf < 4; mf++) {
        int r0 = wm * 64 + mf * 16 + (lane >> 2);
#pragma unroll
        for (int half = 0; half < 2; half++) {
            int rr = r0 + half * 8;
            if (m0 + rr < Me) {
                float* hp = g_h + (size_t)(base + m0 + rr) * H_DIM;
#pragma unroll
                for (int nf = 0; nf < 4; nf++) {
                    int cc = n0 + wn * 32 + nf * 8 + (lane & 3) * 2;
                    float z0 = acc1[mf][nf][half * 2 + 0];
                    float z1 = acc1[mf][nf][half * 2 + 1];
                    uint2 hv;
                    hv.x = f2tf32(z0 / (1.f + __expf(-z0)) * acc3[mf][nf][half * 2 + 0]);
                    hv.y = f2tf32(z1 / (1.f + __expf(-z1)) * acc3[mf][nf][half * 2 + 1]);
                    *reinterpret_cast<uint2*>(hp + cc) = hv;
                }
            }
        }
    }
}

// ================= GEMM2: y = h @ W2  (tile 128x256, 4-stage) =================
#define G2_STAGE 49152
#define G2_SMEM  (4 * G2_STAGE)
__global__ __launch_bounds__(256, 1) void gemm2_wide() {
    const int NT = H_DIM / 32;      // 64 k-tiles
    int e  = blockIdx.y;
    int Me = g_cnt[e];
    int m0 = blockIdx.x * 128;
    if (m0 >= Me) return;
    int n0   = blockIdx.z * 256;
    int base = g_off[e];
    const float* Bm = g_w2T + (size_t)e * D_DIM * H_DIM;

    extern __shared__ char ds[];
    uint32_t sb = smem_u32(ds);
    int tid = threadIdx.x, lane = tid & 31, wid = tid >> 5;
    int wm = wid & 1, wn = wid >> 1;

    const float* aSrc[4]; uint32_t aDst[4];
#pragma unroll
    for (int j = 0; j < 4; j++) {
        int v = tid + j * 256, q = v & 7, m = v >> 3;
        int mg = m0 + m; if (mg > Me - 1) mg = Me - 1;
        aSrc[j] = g_h + (size_t)(base + mg) * H_DIM + q * 4;
        aDst[j] = sb + (uint32_t)(m * 128) + (uint32_t)((q ^ (m & 7)) << 4);
    }
    const float* bSrc[8]; uint32_t bDst[8];
#pragma unroll
    for (int j = 0; j < 8; j++) {
        int v = tid + j * 256, q = v & 7, n = v >> 3;
        bSrc[j] = Bm + (size_t)(n0 + n) * H_DIM + q * 4;
        bDst[j] = sb + 16384u + (uint32_t)(n * 128) + (uint32_t)((q ^ (n & 7)) << 4);
    }

    float acc[4][8][4];
#pragma unroll
    for (int mf = 0; mf < 4; mf++)
#pragma unroll
        for (int nf = 0; nf < 8; nf++)
#pragma unroll
            for (int r = 0; r < 4; r++) acc[mf][nf][r] = 0.f;

#pragma unroll
    for (int s = 0; s < 3; s++) {
        uint32_t bo = (uint32_t)s * G2_STAGE;
        int kof = s * 32;
#pragma unroll
        for (int j = 0; j < 4; j++) CP_ASYNC16(aDst[j] + bo, aSrc[j] + kof);
#pragma unroll
        for (int j = 0; j < 8; j++) CP_ASYNC16(bDst[j] + bo, bSrc[j] + kof);
        CP_COMMIT();
    }

    int arow[4];
#pragma unroll
    for (int mf = 0; mf < 4; mf++)
        arow[mf] = wm * 64 + mf * 16 + (lane & 7) + ((lane >> 3) & 1) * 8;
    int aci = lane >> 4;
    int brow[8];
#pragma unroll
    for (int nf = 0; nf < 8; nf++)
        brow[nf] = wn * 64 + nf * 8 + (lane & 7);
    int bci = (lane >> 3) & 1;

    for (int t = 0; t < NT; t++) {
        CP_WAIT2();
        __syncthreads();
        int ls = t + 3;
        if (ls < NT) {
            uint32_t bo = (uint32_t)(ls & 3) * G2_STAGE;
            int kof = ls * 32;
#pragma unroll
            for (int j = 0; j < 4; j++) CP_ASYNC16(aDst[j] + bo, aSrc[j] + kof);
#pragma unroll
            for (int j = 0; j < 8; j++) CP_ASYNC16(bDst[j] + bo, bSrc[j] + kof);
        }
        CP_COMMIT();

        uint32_t As = sb + (uint32_t)(t & 3) * G2_STAGE;
        uint32_t Bs = As + 16384u;
#pragma unroll
        for (int ks = 0; ks < 4; ks++) {
            uint32_t a[4][4];
#pragma unroll
            for (int mf = 0; mf < 4; mf++) {
                uint32_t ad = As + (uint32_t)(arow[mf] * 128)
                            + (uint32_t)((((2 * ks + aci) ^ (arow[mf] & 7))) << 4);
                LDSM_X4(a[mf], ad);
            }
            uint32_t b[8][2];
#pragma unroll
            for (int nf = 0; nf < 8; nf++) {
                uint32_t bd = Bs + (uint32_t)(brow[nf] * 128)
                            + (uint32_t)((((2 * ks + bci) ^ (brow[nf] & 7))) << 4);
                LDSM_X2(b[nf], bd);
            }
#pragma unroll
            for (int mf = 0; mf < 4; mf++)
#pragma unroll
                for (int nf = 0; nf < 8; nf++)
                    MMA_TF32(acc[mf][nf], a[mf], b[nf]);
        }
    }

#pragma unroll
    for (int mf = 0; mf < 4; mf++) {
        int r0 = wm * 64 + mf * 16 + (lane >> 2);
#pragma unroll
        for (int half = 0; half < 2; half++) {
            int rr = r0 + half * 8;
            if (m0 + rr < Me) {
                size_t rowoff = (size_t)(base + m0 + rr) * D_DIM;
#pragma unroll
                for (int nf = 0; nf < 8; nf++) {
                    int cc = n0 + wn * 64 + nf * 8 + (lane & 3) * 2;
                    float2 v = make_float2(acc[mf][nf][half * 2 + 0],
                                           acc[mf][nf][half * 2 + 1]);
                    *reinterpret_cast<float2*>(g_y + rowoff + cc) = v;
                }
            }
        }
    }
}

// ---------------- combine: out[t] = p0*y[pos0] + p1*y[pos1] ----------------
__global__ void combine_kernel(float* __restrict__ out) {
    int t = blockIdx.x;
    float p0 = g_prob[2 * t], p1 = g_prob[2 * t + 1];
    int   q0 = g_tokpos[2 * t], q1 = g_tokpos[2 * t + 1];
    int i = threadIdx.x * 4;
    float4 a = *reinterpret_cast<const float4*>(g_y + (size_t)q0 * D_DIM + i);
    float4 b = *reinterpret_cast<const float4*>(g_y + (size_t)q1 * D_DIM + i);
    float4 o;
    o.x = p0 * a.x + p1 * b.x;
    o.y = p0 * a.y + p1 * b.y;
    o.z = p0 * a.z + p1 * b.z;
    o.w = p0 * a.w + p1 * b.w;
    *reinterpret_cast<float4*>(out + (size_t)t * D_DIM + i) = o;
}

// ---------------- launch ----------------
extern "C" void kernel_launch(void* const* d_in, const int* in_sizes, int n_in,
                              void* d_out, int out_size) {
    const float* x  = (const float*)d_in[0];   // (B,S,D)
    const float* wg = (const float*)d_in[1];   // (D,E)
    const float* w1 = (const float*)d_in[2];   // (E,D,H)
    const float* w3 = (const float*)d_in[3];   // (E,D,H)
    const float* w2 = (const float*)d_in[4];   // (E,H,D)
    float* out = (float*)d_out;
    (void)in_sizes; (void)n_in; (void)out_size;

    cudaFuncSetAttribute(gemm1_fused, cudaFuncAttributeMaxDynamicSharedMemorySize, G1_SMEM);
    cudaFuncSetAttribute(gemm2_wide,  cudaFuncAttributeMaxDynamicSharedMemorySize, G2_SMEM);

    void *p_xc, *p_w1T, *p_w3T, *p_w2T;
    cudaGetSymbolAddress(&p_xc,  g_xc);
    cudaGetSymbolAddress(&p_w1T, g_w1T);
    cudaGetSymbolAddress(&p_w3T, g_w3T);
    cudaGetSymbolAddress(&p_w2T, g_w2T);

    init_kernel<<<1, 32>>>();
    cvt_x_kernel<<<(T_TOK * D_DIM / 4) / 256, 256>>>(x);

    dim3 tb(32, 8);
    transpose_cvt_kernel<<<dim3(H_DIM / 32, D_DIM / 32, E_NUM), tb>>>(w1, (float*)p_w1T, D_DIM, H_DIM);
    transpose_cvt_kernel<<<dim3(H_DIM / 32, D_DIM / 32, E_NUM), tb>>>(w3, (float*)p_w3T, D_DIM, H_DIM);
    transpose_cvt_kernel<<<dim3(D_DIM / 32, H_DIM / 32, E_NUM), tb>>>(w2, (float*)p_w2T, H_DIM, D_DIM);

    gate_kernel<<<(T_TOK * 32 + 255) / 256, 256>>>(x, wg);
    offsets_kernel<<<1, 32>>>();
    scatter_kernel<<<(T_TOK + 255) / 256, 256>>>();

    dim3 g1(NA / 128, E_NUM, H_DIM / 128);   // (128, 8, 16)
    gemm1_fused<<<g1, 256, G1_SMEM>>>((const float*)p_xc);

    dim3 g2(NA / 128, E_NUM, D_DIM / 256);   // (128, 8, 4)
    gemm2_wide<<<g2, 256, G2_SMEM>>>();

    combine_kernel<<<T_TOK, 256>>>(out);
}

// round 9
// speedup vs baseline: 1.0359x; 1.0359x over previous
#include <cuda_runtime.h>
#include <math.h>
#include <stdint.h>

#define T_TOK 8192
#define D_DIM 1024
#define H_DIM 2048
#define E_NUM 8
#define NA (T_TOK * 2)

// ---------------- scratch (device globals; no allocation) ----------------
__device__ int   g_cnt[E_NUM];
__device__ int   g_off[E_NUM];
__device__ int   g_cur[E_NUM];
__device__ int   g_sel[NA];
__device__ float g_prob[NA];
__device__ int   g_rows[NA];
__device__ int   g_tokpos[NA];
__device__ float g_xc[(size_t)T_TOK * D_DIM];                //  32 MB tf32 x
__device__ float g_h [(size_t)NA * H_DIM];                   // 128 MB silu product (tf32)
__device__ float g_y [(size_t)NA * D_DIM];                   //  64 MB expert outputs
__device__ float g_w1T[(size_t)E_NUM * H_DIM * D_DIM];       //  64 MB [e][h][d] tf32
__device__ float g_w3T[(size_t)E_NUM * H_DIM * D_DIM];       //  64 MB [e][h][d] tf32
__device__ float g_w2T[(size_t)E_NUM * D_DIM * H_DIM];       //  64 MB [e][d][h] tf32

// ================= helpers =================
__device__ __forceinline__ uint32_t smem_u32(const void* p) {
    uint32_t a;
    asm("{ .reg .u64 t; cvta.to.shared.u64 t, %1; cvt.u32.u64 %0, t; }" : "=r"(a) : "l"(p));
    return a;
}
__device__ __forceinline__ uint32_t f2tf32(float x) {
    uint32_t u;
    asm("cvt.rna.tf32.f32 %0, %1;" : "=r"(u) : "f"(x));
    return u;
}

#define CP_ASYNC16(dst, src) \
    asm volatile("cp.async.cg.shared.global [%0], [%1], 16;" :: "r"(dst), "l"(src) : "memory")
#define CP_COMMIT() asm volatile("cp.async.commit_group;" ::: "memory")
#define CP_WAIT1()  asm volatile("cp.async.wait_group 1;" ::: "memory")

#define LDSM_X4(r, addr) \
    asm volatile("ldmatrix.sync.aligned.m8n8.x4.shared.b16 {%0,%1,%2,%3}, [%4];" \
        : "=r"((r)[0]), "=r"((r)[1]), "=r"((r)[2]), "=r"((r)[3]) : "r"(addr))
#define LDSM_X2(r, addr) \
    asm volatile("ldmatrix.sync.aligned.m8n8.x2.shared.b16 {%0,%1}, [%2];" \
        : "=r"((r)[0]), "=r"((r)[1]) : "r"(addr))

#define MMA_TF32(d, a, b) \
    asm volatile("mma.sync.aligned.m16n8k8.row.col.f32.tf32.tf32.f32 " \
        "{%0,%1,%2,%3}, {%4,%5,%6,%7}, {%8,%9}, {%0,%1,%2,%3};" \
        : "+f"((d)[0]), "+f"((d)[1]), "+f"((d)[2]), "+f"((d)[3]) \
        : "r"((a)[0]), "r"((a)[1]), "r"((a)[2]), "r"((a)[3]), "r"((b)[0]), "r"((b)[1]))

// ---------------- init ----------------
__global__ void init_kernel() {
    int i = threadIdx.x;
    if (i < E_NUM) { g_cnt[i] = 0; g_cur[i] = 0; }
}

// ---------------- x -> tf32 copy ----------------
__global__ void cvt_x_kernel(const float* __restrict__ x) {
    size_t i = ((size_t)blockIdx.x * blockDim.x + threadIdx.x) * 4;
    float4 v = *reinterpret_cast<const float4*>(x + i);
    uint4 o;
    o.x = f2tf32(v.x); o.y = f2tf32(v.y); o.z = f2tf32(v.z); o.w = f2tf32(v.w);
    *reinterpret_cast<uint4*>(g_xc + i) = o;
}

// ---------------- weight transpose + tf32 round: [E][R][C] -> [E][C][R] ----------------
__global__ void transpose_cvt_kernel(const float* __restrict__ src, float* __restrict__ dst,
                                     int R, int C) {
    __shared__ float tile[32][33];
    size_t eoff = (size_t)blockIdx.z * R * C;
    src += eoff; dst += eoff;
    int c0 = blockIdx.x * 32, r0 = blockIdx.y * 32;
    int tx = threadIdx.x, ty = threadIdx.y;
#pragma unroll
    for (int i = 0; i < 4; i++)
        tile[ty + i * 8][tx] = src[(size_t)(r0 + ty + i * 8) * C + c0 + tx];
    __syncthreads();
#pragma unroll
    for (int i = 0; i < 4; i++)
        dst[(size_t)(c0 + ty + i * 8) * R + r0 + tx] =
            __uint_as_float(f2tf32(tile[tx][ty + i * 8]));
}

// ---------------- gating: warp per token (exact fp32) ----------------
__global__ void gate_kernel(const float* __restrict__ x, const float* __restrict__ wg) {
    int warp = (blockIdx.x * blockDim.x + threadIdx.x) >> 5;
    int lane = threadIdx.x & 31;
    if (warp >= T_TOK) return;
    const float* xr = x + (size_t)warp * D_DIM;
    float acc[E_NUM];
#pragma unroll
    for (int e = 0; e < E_NUM; e++) acc[e] = 0.f;
    for (int d = lane; d < D_DIM; d += 32) {
        float xv = xr[d];
        const float* w = wg + (size_t)d * E_NUM;
#pragma unroll
        for (int e = 0; e < E_NUM; e++) acc[e] += xv * w[e];
    }
#pragma unroll
    for (int e = 0; e < E_NUM; e++) {
#pragma unroll
        for (int o = 16; o > 0; o >>= 1)
            acc[e] += __shfl_xor_sync(0xffffffff, acc[e], o);
    }
    if (lane == 0) {
        float best = -1e30f, sec = -1e30f;
        int bi = 0, si = 0;
#pragma unroll
        for (int e = 0; e < E_NUM; e++) {
            float v = acc[e];
            if (v > best) { sec = best; si = bi; best = v; bi = e; }
            else if (v > sec) { sec = v; si = e; }
        }
        float p0 = 1.f / (1.f + expf(sec - best));
        g_sel[warp * 2]      = bi;
        g_sel[warp * 2 + 1]  = si;
        g_prob[warp * 2]     = p0;
        g_prob[warp * 2 + 1] = 1.f - p0;
        atomicAdd(&g_cnt[bi], 1);
        atomicAdd(&g_cnt[si], 1);
    }
}

__global__ void offsets_kernel() {
    if (threadIdx.x == 0) {
        int r = 0;
        for (int e = 0; e < E_NUM; e++) { g_off[e] = r; g_cur[e] = r; r += g_cnt[e]; }
    }
}

__global__ void scatter_kernel() {
    int t = blockIdx.x * blockDim.x + threadIdx.x;
    if (t >= T_TOK) return;
#pragma unroll
    for (int k = 0; k < 2; k++) {
        int e = g_sel[t * 2 + k];
        int pos = atomicAdd(&g_cur[e], 1);
        g_rows[pos]         = t;
        g_tokpos[t * 2 + k] = pos;
    }
}

// ================= GEMM1 fused: h = silu(Xg@W1)*(Xg@W3), 512 thr, 3-stage =================
// CTA tile M=128, N=128 vs BOTH W1,W3. 16 warps (4m x 4n), warp tile 32x32 per matrix.
// Stage = A(16K)+B1(16K)+B3(16K) = 48K; 3 stages = 144K.
#define G1_STAGE 49152
#define G1_SMEM  (3 * G1_STAGE)
__global__ __launch_bounds__(512, 1) void gemm1_fused(const float* __restrict__ Abase) {
    const int NT = D_DIM / 32;      // 32 k-tiles
    int e  = blockIdx.y;
    int Me = g_cnt[e];
    int m0 = blockIdx.x * 128;
    if (m0 >= Me) return;
    int n0   = blockIdx.z * 128;
    int base = g_off[e];
    const float* B1m = g_w1T + (size_t)e * H_DIM * D_DIM;
    const float* B3m = g_w3T + (size_t)e * H_DIM * D_DIM;

    extern __shared__ char ds[];
    uint32_t sb = smem_u32(ds);
    int tid = threadIdx.x, lane = tid & 31, wid = tid >> 5;
    int wm = wid & 3, wn = wid >> 2;

    // loaders: A/B1/B3 each 128 rows x 32k floats = 1024 float4 -> 2 per thread
    const float* aSrc[2];  uint32_t aDst[2];
    const float* b1Src[2]; const float* b3Src[2]; uint32_t bDst[2];
#pragma unroll
    for (int j = 0; j < 2; j++) {
        int v = tid + j * 512, q = v & 7, m = v >> 3;
        int mg = m0 + m; if (mg > Me - 1) mg = Me - 1;
        aSrc[j]  = Abase + (size_t)g_rows[base + mg] * D_DIM + q * 4;
        b1Src[j] = B1m + (size_t)(n0 + m) * D_DIM + q * 4;
        b3Src[j] = B3m + (size_t)(n0 + m) * D_DIM + q * 4;
        uint32_t off = (uint32_t)(m * 128) + (uint32_t)((q ^ (m & 7)) << 4);
        aDst[j] = sb + off;
        bDst[j] = sb + 16384u + off;
    }

    float acc1[2][4][4], acc3[2][4][4];
#pragma unroll
    for (int mf = 0; mf < 2; mf++)
#pragma unroll
        for (int nf = 0; nf < 4; nf++)
#pragma unroll
            for (int r = 0; r < 4; r++) { acc1[mf][nf][r] = 0.f; acc3[mf][nf][r] = 0.f; }

    // prologue: stages 0,1
#pragma unroll
    for (int s = 0; s < 2; s++) {
        uint32_t bo = (uint32_t)s * G1_STAGE;
        int kof = s * 32;
#pragma unroll
        for (int j = 0; j < 2; j++) {
            CP_ASYNC16(aDst[j] + bo,          aSrc[j]  + kof);
            CP_ASYNC16(bDst[j] + bo,          b1Src[j] + kof);
            CP_ASYNC16(bDst[j] + bo + 16384u, b3Src[j] + kof);
        }
        CP_COMMIT();
    }

    int arow[2];
#pragma unroll
    for (int mf = 0; mf < 2; mf++)
        arow[mf] = wm * 32 + mf * 16 + (lane & 7) + ((lane >> 3) & 1) * 8;
    int aci = lane >> 4;
    int brow[4];
#pragma unroll
    for (int nf = 0; nf < 4; nf++)
        brow[nf] = wn * 32 + nf * 8 + (lane & 7);
    int bci = (lane >> 3) & 1;

    int bufc = 0, bufl = 2;        // compute buf, load buf (mod 3)
    for (int t = 0; t < NT; t++) {
        CP_WAIT1();                // stage t complete (t+1 may be pending)
        __syncthreads();           // all warps done with the buf we overwrite next
        int ls = t + 2;
        if (ls < NT) {
            uint32_t bo = (uint32_t)bufl * G1_STAGE;
            int kof = ls * 32;
#pragma unroll
            for (int j = 0; j < 2; j++) {
                CP_ASYNC16(aDst[j] + bo,          aSrc[j]  + kof);
                CP_ASYNC16(bDst[j] + bo,          b1Src[j] + kof);
                CP_ASYNC16(bDst[j] + bo + 16384u, b3Src[j] + kof);
            }
        }
        CP_COMMIT();
        if (++bufl == 3) bufl = 0;

        uint32_t As  = sb + (uint32_t)bufc * G1_STAGE;
        uint32_t B1s = As + 16384u;
        uint32_t B3s = As + 32768u;
        if (++bufc == 3) bufc = 0;
#pragma unroll
        for (int ks = 0; ks < 4; ks++) {
            uint32_t a[2][4];
#pragma unroll
            for (int mf = 0; mf < 2; mf++) {
                uint32_t ad = As + (uint32_t)(arow[mf] * 128)
                            + (uint32_t)((((2 * ks + aci) ^ (arow[mf] & 7))) << 4);
                LDSM_X4(a[mf], ad);
            }
            uint32_t b1[4][2], b3[4][2];
#pragma unroll
            for (int nf = 0; nf < 4; nf++) {
                uint32_t co = (uint32_t)((((2 * ks + bci) ^ (brow[nf] & 7))) << 4);
                uint32_t ro = (uint32_t)(brow[nf] * 128);
                LDSM_X2(b1[nf], B1s + ro + co);
                LDSM_X2(b3[nf], B3s + ro + co);
            }
#pragma unroll
            for (int mf = 0; mf < 2; mf++)
#pragma unroll
                for (int nf = 0; nf < 4; nf++) {
                    MMA_TF32(acc1[mf][nf], a[mf], b1[nf]);
                    MMA_TF32(acc3[mf][nf], a[mf], b3[nf]);
                }
        }
    }

    // epilogue: silu(t1)*t3 -> g_h (tf32)
#pragma unroll
    for (int mf = 0; mf < 2; mf++) {
        int r0 = wm * 32 + mf * 16 + (lane >> 2);
#pragma unroll
        for (int half = 0; half < 2; half++) {
            int rr = r0 + half * 8;
            if (m0 + rr < Me) {
                float* hp = g_h + (size_t)(base + m0 + rr) * H_DIM;
#pragma unroll
                for (int nf = 0; nf < 4; nf++) {
                    int cc = n0 + wn * 32 + nf * 8 + (lane & 3) * 2;
                    float z0 = acc1[mf][nf][half * 2 + 0];
                    float z1 = acc1[mf][nf][half * 2 + 1];
                    uint2 hv;
                    hv.x = f2tf32(z0 / (1.f + __expf(-z0)) * acc3[mf][nf][half * 2 + 0]);
                    hv.y = f2tf32(z1 / (1.f + __expf(-z1)) * acc3[mf][nf][half * 2 + 1]);
                    *reinterpret_cast<uint2*>(hp + cc) = hv;
                }
            }
        }
    }
}

// ================= GEMM2: y = h @ W2  (tile 128x256, 512 thr, 3-stage) =================
#define G2_STAGE 49152
#define G2_SMEM  (3 * G2_STAGE)
__global__ __launch_bounds__(512, 1) void gemm2_wide() {
    const int NT = H_DIM / 32;      // 64 k-tiles
    int e  = blockIdx.y;
    int Me = g_cnt[e];
    int m0 = blockIdx.x * 128;
    if (m0 >= Me) return;
    int n0   = blockIdx.z * 256;
    int base = g_off[e];
    const float* Bm = g_w2T + (size_t)e * D_DIM * H_DIM;

    extern __shared__ char ds[];
    uint32_t sb = smem_u32(ds);
    int tid = threadIdx.x, lane = tid & 31, wid = tid >> 5;
    int wm = wid & 3, wn = wid >> 2;

    // A: 128x32 = 1024 float4 -> 2/thread; B: 256x32 = 2048 float4 -> 4/thread
    const float* aSrc[2]; uint32_t aDst[2];
#pragma unroll
    for (int j = 0; j < 2; j++) {
        int v = tid + j * 512, q = v & 7, m = v >> 3;
        int mg = m0 + m; if (mg > Me - 1) mg = Me - 1;
        aSrc[j] = g_h + (size_t)(base + mg) * H_DIM + q * 4;
        aDst[j] = sb + (uint32_t)(m * 128) + (uint32_t)((q ^ (m & 7)) << 4);
    }
    const float* bSrc[4]; uint32_t bDst[4];
#pragma unroll
    for (int j = 0; j < 4; j++) {
        int v = tid + j * 512, q = v & 7, n = v >> 3;
        bSrc[j] = Bm + (size_t)(n0 + n) * H_DIM + q * 4;
        bDst[j] = sb + 16384u + (uint32_t)(n * 128) + (uint32_t)((q ^ (n & 7)) << 4);
    }

    float acc[2][8][4];
#pragma unroll
    for (int mf = 0; mf < 2; mf++)
#pragma unroll
        for (int nf = 0; nf < 8; nf++)
#pragma unroll
            for (int r = 0; r < 4; r++) acc[mf][nf][r] = 0.f;

#pragma unroll
    for (int s = 0; s < 2; s++) {
        uint32_t bo = (uint32_t)s * G2_STAGE;
        int kof = s * 32;
#pragma unroll
        for (int j = 0; j < 2; j++) CP_ASYNC16(aDst[j] + bo, aSrc[j] + kof);
#pragma unroll
        for (int j = 0; j < 4; j++) CP_ASYNC16(bDst[j] + bo, bSrc[j] + kof);
        CP_COMMIT();
    }

    int arow[2];
#pragma unroll
    for (int mf = 0; mf < 2; mf++)
        arow[mf] = wm * 32 + mf * 16 + (lane & 7) + ((lane >> 3) & 1) * 8;
    int aci = lane >> 4;
    int brow[8];
#pragma unroll
    for (int nf = 0; nf < 8; nf++)
        brow[nf] = wn * 64 + nf * 8 + (lane & 7);
    int bci = (lane >> 3) & 1;

    int bufc = 0, bufl = 2;
    for (int t = 0; t < NT; t++) {
        CP_WAIT1();
        __syncthreads();
        int ls = t + 2;
        if (ls < NT) {
            uint32_t bo = (uint32_t)bufl * G2_STAGE;
            int kof = ls * 32;
#pragma unroll
            for (int j = 0; j < 2; j++) CP_ASYNC16(aDst[j] + bo, aSrc[j] + kof);
#pragma unroll
            for (int j = 0; j < 4; j++) CP_ASYNC16(bDst[j] + bo, bSrc[j] + kof);
        }
        CP_COMMIT();
        if (++bufl == 3) bufl = 0;

        uint32_t As = sb + (uint32_t)bufc * G2_STAGE;
        uint32_t Bs = As + 16384u;
        if (++bufc == 3) bufc = 0;
#pragma unroll
        for (int ks = 0; ks < 4; ks++) {
            uint32_t a[2][4];
#pragma unroll
            for (int mf = 0; mf < 2; mf++) {
                uint32_t ad = As + (uint32_t)(arow[mf] * 128)
                            + (uint32_t)((((2 * ks + aci) ^ (arow[mf] & 7))) << 4);
                LDSM_X4(a[mf], ad);
            }
            uint32_t b[8][2];
#pragma unroll
            for (int nf = 0; nf < 8; nf++) {
                uint32_t bd = Bs + (uint32_t)(brow[nf] * 128)
                            + (uint32_t)((((2 * ks + bci) ^ (brow[nf] & 7))) << 4);
                LDSM_X2(b[nf], bd);
            }
#pragma unroll
            for (int mf = 0; mf < 2; mf++)
#pragma unroll
                for (int nf = 0; nf < 8; nf++)
                    MMA_TF32(acc[mf][nf], a[mf], b[nf]);
        }
    }

#pragma unroll
    for (int mf = 0; mf < 2; mf++) {
        int r0 = wm * 32 + mf * 16 + (lane >> 2);
#pragma unroll
        for (int half = 0; half < 2; half++) {
            int rr = r0 + half * 8;
            if (m0 + rr < Me) {
                size_t rowoff = (size_t)(base + m0 + rr) * D_DIM;
#pragma unroll
                for (int nf = 0; nf < 8; nf++) {
                    int cc = n0 + wn * 64 + nf * 8 + (lane & 3) * 2;
                    float2 v = make_float2(acc[mf][nf][half * 2 + 0],
                                           acc[mf][nf][half * 2 + 1]);
                    *reinterpret_cast<float2*>(g_y + rowoff + cc) = v;
                }
            }
        }
    }
}

// ---------------- combine: out[t] = p0*y[pos0] + p1*y[pos1] ----------------
__global__ void combine_kernel(float* __restrict__ out) {
    int t = blockIdx.x;
    float p0 = g_prob[2 * t], p1 = g_prob[2 * t + 1];
    int   q0 = g_tokpos[2 * t], q1 = g_tokpos[2 * t + 1];
    int i = threadIdx.x * 4;
    float4 a = *reinterpret_cast<const float4*>(g_y + (size_t)q0 * D_DIM + i);
    float4 b = *reinterpret_cast<const float4*>(g_y + (size_t)q1 * D_DIM + i);
    float4 o;
    o.x = p0 * a.x + p1 * b.x;
    o.y = p0 * a.y + p1 * b.y;
    o.z = p0 * a.z + p1 * b.z;
    o.w = p0 * a.w + p1 * b.w;
    *reinterpret_cast<float4*>(out + (size_t)t * D_DIM + i) = o;
}

// ---------------- launch ----------------
extern "C" void kernel_launch(void* const* d_in, const int* in_sizes, int n_in,
                              void* d_out, int out_size) {
    const float* x  = (const float*)d_in[0];   // (B,S,D)
    const float* wg = (const float*)d_in[1];   // (D,E)
    const float* w1 = (const float*)d_in[2];   // (E,D,H)
    const float* w3 = (const float*)d_in[3];   // (E,D,H)
    const float* w2 = (const float*)d_in[4];   // (E,H,D)
    float* out = (float*)d_out;
    (void)in_sizes; (void)n_in; (void)out_size;

    cudaFuncSetAttribute(gemm1_fused, cudaFuncAttributeMaxDynamicSharedMemorySize, G1_SMEM);
    cudaFuncSetAttribute(gemm2_wide,  cudaFuncAttributeMaxDynamicSharedMemorySize, G2_SMEM);

    void *p_xc, *p_w1T, *p_w3T, *p_w2T;
    cudaGetSymbolAddress(&p_xc,  g_xc);
    cudaGetSymbolAddress(&p_w1T, g_w1T);
    cudaGetSymbolAddress(&p_w3T, g_w3T);
    cudaGetSymbolAddress(&p_w2T, g_w2T);

    init_kernel<<<1, 32>>>();
    cvt_x_kernel<<<(T_TOK * D_DIM / 4) / 256, 256>>>(x);

    dim3 tb(32, 8);
    transpose_cvt_kernel<<<dim3(H_DIM / 32, D_DIM / 32, E_NUM), tb>>>(w1, (float*)p_w1T, D_DIM, H_DIM);
    transpose_cvt_kernel<<<dim3(H_DIM / 32, D_DIM / 32, E_NUM), tb>>>(w3, (float*)p_w3T, D_DIM, H_DIM);
    transpose_cvt_kernel<<<dim3(D_DIM / 32, H_DIM / 32, E_NUM), tb>>>(w2, (float*)p_w2T, H_DIM, D_DIM);

    gate_kernel<<<(T_TOK * 32 + 255) / 256, 256>>>(x, wg);
    offsets_kernel<<<1, 32>>>();
    scatter_kernel<<<(T_TOK + 255) / 256, 256>>>();

    dim3 g1(NA / 128, E_NUM, H_DIM / 128);   // (128, 8, 16)
    gemm1_fused<<<g1, 512, G1_SMEM>>>((const float*)p_xc);

    dim3 g2(NA / 128, E_NUM, D_DIM / 256);   // (128, 8, 4)
    gemm2_wide<<<g2, 512, G2_SMEM>>>();

    combine_kernel<<<T_TOK, 256>>>(out);
}

// round 11
// speedup vs baseline: 1.7335x; 1.6734x over previous
#include <cuda_runtime.h>
#include <cuda_fp16.h>
#include <math.h>
#include <stdint.h>

#define T_TOK 8192
#define D_DIM 1024
#define H_DIM 2048
#define E_NUM 8
#define NA (T_TOK * 2)

// ---------------- scratch (device globals; no allocation) ----------------
__device__ int    g_cnt[E_NUM];
__device__ int    g_off[E_NUM];
__device__ int    g_cur[E_NUM];
__device__ int    g_sel[NA];
__device__ float  g_prob[NA];
__device__ int    g_rows[NA];
__device__ int    g_tokpos[NA];
__device__ __half g_xc[(size_t)T_TOK * D_DIM];                //  16 MB fp16 x
__device__ __half g_h [(size_t)NA * H_DIM];                   //  64 MB fp16 silu product
__device__ float  g_y [(size_t)NA * D_DIM];                   //  64 MB expert outputs (fp32)
__device__ __half g_w1T[(size_t)E_NUM * H_DIM * D_DIM];       //  32 MB [e][h][d] fp16
__device__ __half g_w3T[(size_t)E_NUM * H_DIM * D_DIM];       //  32 MB [e][h][d] fp16
__device__ __half g_w2T[(size_t)E_NUM * D_DIM * H_DIM];       //  32 MB [e][d][h] fp16

// ================= helpers =================
__device__ __forceinline__ uint32_t smem_u32(const void* p) {
    uint32_t a;
    asm("{ .reg .u64 t; cvta.to.shared.u64 t, %1; cvt.u32.u64 %0, t; }" : "=r"(a) : "l"(p));
    return a;
}
__device__ __forceinline__ uint32_t pack_half2(float lo, float hi) {
    __half2 h = __floats2half2_rn(lo, hi);
    uint32_t u;
    memcpy(&u, &h, 4);
    return u;
}

#define CP_ASYNC16(dst, src) \
    asm volatile("cp.async.cg.shared.global [%0], [%1], 16;" :: "r"(dst), "l"(src) : "memory")
#define CP_COMMIT() asm volatile("cp.async.commit_group;" ::: "memory")
#define CP_WAIT1()  asm volatile("cp.async.wait_group 1;" ::: "memory")

#define LDSM_X4(r, addr) \
    asm volatile("ldmatrix.sync.aligned.m8n8.x4.shared.b16 {%0,%1,%2,%3}, [%4];" \
        : "=r"((r)[0]), "=r"((r)[1]), "=r"((r)[2]), "=r"((r)[3]) : "r"(addr))
#define LDSM_X2(r, addr) \
    asm volatile("ldmatrix.sync.aligned.m8n8.x2.shared.b16 {%0,%1}, [%2];" \
        : "=r"((r)[0]), "=r"((r)[1]) : "r"(addr))

// fp16 MMA, fp32 accumulate: 16x8x16
#define MMA_F16(d, a, b) \
    asm volatile("mma.sync.aligned.m16n8k16.row.col.f32.f16.f16.f32 " \
        "{%0,%1,%2,%3}, {%4,%5,%6,%7}, {%8,%9}, {%0,%1,%2,%3};" \
        : "+f"((d)[0]), "+f"((d)[1]), "+f"((d)[2]), "+f"((d)[3]) \
        : "r"((a)[0]), "r"((a)[1]), "r"((a)[2]), "r"((a)[3]), "r"((b)[0]), "r"((b)[1]))

// ---------------- init ----------------
__global__ void init_kernel() {
    int i = threadIdx.x;
    if (i < E_NUM) { g_cnt[i] = 0; g_cur[i] = 0; }
}

// ---------------- x -> fp16 copy (8 elems/thread) ----------------
__global__ void cvt_x_kernel(const float* __restrict__ x) {
    size_t i = ((size_t)blockIdx.x * blockDim.x + threadIdx.x) * 8;
    float4 v0 = *reinterpret_cast<const float4*>(x + i);
    float4 v1 = *reinterpret_cast<const float4*>(x + i + 4);
    uint4 o;
    o.x = pack_half2(v0.x, v0.y);
    o.y = pack_half2(v0.z, v0.w);
    o.z = pack_half2(v1.x, v1.y);
    o.w = pack_half2(v1.z, v1.w);
    *reinterpret_cast<uint4*>(g_xc + i) = o;
}

// ---------------- weight transpose + fp16 round: [E][R][C] -> [E][C][R] ----------------
__global__ void transpose_cvt_kernel(const float* __restrict__ src, __half* __restrict__ dst,
                                     int R, int C) {
    __shared__ float tile[32][33];
    src += (size_t)blockIdx.z * R * C;
    dst += (size_t)blockIdx.z * R * C;
    int c0 = blockIdx.x * 32, r0 = blockIdx.y * 32;
    int tx = threadIdx.x, ty = threadIdx.y;
#pragma unroll
    for (int i = 0; i < 4; i++)
        tile[ty + i * 8][tx] = src[(size_t)(r0 + ty + i * 8) * C + c0 + tx];
    __syncthreads();
#pragma unroll
    for (int i = 0; i < 4; i++)
        dst[(size_t)(c0 + ty + i * 8) * R + r0 + tx] = __float2half_rn(tile[tx][ty + i * 8]);
}

// ---------------- gating: warp per token (exact fp32) ----------------
__global__ void gate_kernel(const float* __restrict__ x, const float* __restrict__ wg) {
    int warp = (blockIdx.x * blockDim.x + threadIdx.x) >> 5;
    int lane = threadIdx.x & 31;
    if (warp >= T_TOK) return;
    const float* xr = x + (size_t)warp * D_DIM;
    float acc[E_NUM];
#pragma unroll
    for (int e = 0; e < E_NUM; e++) acc[e] = 0.f;
    for (int d = lane; d < D_DIM; d += 32) {
        float xv = xr[d];
        const float* w = wg + (size_t)d * E_NUM;
#pragma unroll
        for (int e = 0; e < E_NUM; e++) acc[e] += xv * w[e];
    }
#pragma unroll
    for (int e = 0; e < E_NUM; e++) {
#pragma unroll
        for (int o = 16; o > 0; o >>= 1)
            acc[e] += __shfl_xor_sync(0xffffffff, acc[e], o);
    }
    if (lane == 0) {
        float best = -1e30f, sec = -1e30f;
        int bi = 0, si = 0;
#pragma unroll
        for (int e = 0; e < E_NUM; e++) {
            float v = acc[e];
            if (v > best) { sec = best; si = bi; best = v; bi = e; }
            else if (v > sec) { sec = v; si = e; }
        }
        float p0 = 1.f / (1.f + expf(sec - best));
        g_sel[warp * 2]      = bi;
        g_sel[warp * 2 + 1]  = si;
        g_prob[warp * 2]     = p0;
        g_prob[warp * 2 + 1] = 1.f - p0;
        atomicAdd(&g_cnt[bi], 1);
        atomicAdd(&g_cnt[si], 1);
    }
}

__global__ void offsets_kernel() {
    if (threadIdx.x == 0) {
        int r = 0;
        for (int e = 0; e < E_NUM; e++) { g_off[e] = r; g_cur[e] = r; r += g_cnt[e]; }
    }
}

__global__ void scatter_kernel() {
    int t = blockIdx.x * blockDim.x + threadIdx.x;
    if (t >= T_TOK) return;
#pragma unroll
    for (int k = 0; k < 2; k++) {
        int e = g_sel[t * 2 + k];
        int pos = atomicAdd(&g_cur[e], 1);
        g_rows[pos]         = t;
        g_tokpos[t * 2 + k] = pos;
    }
}

// ================= GEMM1 fused: h = silu(Xg@W1)*(Xg@W3), fp16 m16n8k16 =================
// CTA tile M=128, N=128 vs BOTH W1,W3. 16 warps (4m x 4n), warp tile 32x32 per matrix.
// BK=64 halves = 128B rows (SW128 swizzle). Stage = A(16K)+B1(16K)+B3(16K)=48K; 3 stages.
#define G1_STAGE 49152
#define G1_SMEM  (3 * G1_STAGE)
__global__ __launch_bounds__(512, 1) void gemm1_fused() {
    const int NT = D_DIM / 64;      // 16 k-tiles
    int e  = blockIdx.y;
    int Me = g_cnt[e];
    int m0 = blockIdx.x * 128;
    if (m0 >= Me) return;
    int n0   = blockIdx.z * 128;
    int base = g_off[e];
    const __half* B1m = g_w1T + (size_t)e * H_DIM * D_DIM;
    const __half* B3m = g_w3T + (size_t)e * H_DIM * D_DIM;

    extern __shared__ char ds[];
    uint32_t sb = smem_u32(ds);
    int tid = threadIdx.x, lane = tid & 31, wid = tid >> 5;
    int wm = wid & 3, wn = wid >> 2;

    // loaders: 128 rows x 8 chunks (16B = 8 halves) = 1024 -> 2 per thread
    const __half* aSrc[2]; const __half* b1Src[2]; const __half* b3Src[2];
    uint32_t aDst[2], bDst[2];
#pragma unroll
    for (int j = 0; j < 2; j++) {
        int v = tid + j * 512, q = v & 7, m = v >> 3;
        int mg = m0 + m; if (mg > Me - 1) mg = Me - 1;
        aSrc[j]  = g_xc + (size_t)g_rows[base + mg] * D_DIM + q * 8;
        b1Src[j] = B1m + (size_t)(n0 + m) * D_DIM + q * 8;
        b3Src[j] = B3m + (size_t)(n0 + m) * D_DIM + q * 8;
        uint32_t off = (uint32_t)(m * 128) + (uint32_t)((q ^ (m & 7)) << 4);
        aDst[j] = sb + off;
        bDst[j] = sb + 16384u + off;
    }

    float acc1[2][4][4], acc3[2][4][4];
#pragma unroll
    for (int mf = 0; mf < 2; mf++)
#pragma unroll
        for (int nf = 0; nf < 4; nf++)
#pragma unroll
            for (int r = 0; r < 4; r++) { acc1[mf][nf][r] = 0.f; acc3[mf][nf][r] = 0.f; }

    // prologue: stages 0,1
#pragma unroll
    for (int s = 0; s < 2; s++) {
        uint32_t bo = (uint32_t)s * G1_STAGE;
        int kof = s * 64;
#pragma unroll
        for (int j = 0; j < 2; j++) {
            CP_ASYNC16(aDst[j] + bo,          aSrc[j]  + kof);
            CP_ASYNC16(bDst[j] + bo,          b1Src[j] + kof);
            CP_ASYNC16(bDst[j] + bo + 16384u, b3Src[j] + kof);
        }
        CP_COMMIT();
    }

    int arow[2];
#pragma unroll
    for (int mf = 0; mf < 2; mf++)
        arow[mf] = wm * 32 + mf * 16 + (lane & 15);
    int aci = lane >> 4;           // k8-chunk select within k16 step
    int brow[4];
#pragma unroll
    for (int nf = 0; nf < 4; nf++)
        brow[nf] = wn * 32 + nf * 8 + (lane & 7);
    int bci = (lane >> 3) & 1;

    int bufc = 0, bufl = 2;
    for (int t = 0; t < NT; t++) {
        CP_WAIT1();
        __syncthreads();
        int ls = t + 2;
        if (ls < NT) {
            uint32_t bo = (uint32_t)bufl * G1_STAGE;
            int kof = ls * 64;
#pragma unroll
            for (int j = 0; j < 2; j++) {
                CP_ASYNC16(aDst[j] + bo,          aSrc[j]  + kof);
                CP_ASYNC16(bDst[j] + bo,          b1Src[j] + kof);
                CP_ASYNC16(bDst[j] + bo + 16384u, b3Src[j] + kof);
            }
        }
        CP_COMMIT();
        if (++bufl == 3) bufl = 0;

        uint32_t As  = sb + (uint32_t)bufc * G1_STAGE;
        uint32_t B1s = As + 16384u;
        uint32_t B3s = As + 32768u;
        if (++bufc == 3) bufc = 0;
#pragma unroll
        for (int ks = 0; ks < 4; ks++) {   // 4 x k16 = 64
            uint32_t a[2][4];
#pragma unroll
            for (int mf = 0; mf < 2; mf++) {
                uint32_t ad = As + (uint32_t)(arow[mf] * 128)
                            + (uint32_t)((((2 * ks + aci) ^ (arow[mf] & 7))) << 4);
                LDSM_X4(a[mf], ad);
            }
            uint32_t b1[4][2], b3[4][2];
#pragma unroll
            for (int nf = 0; nf < 4; nf++) {
                uint32_t co = (uint32_t)((((2 * ks + bci) ^ (brow[nf] & 7))) << 4);
                uint32_t ro = (uint32_t)(brow[nf] * 128);
                LDSM_X2(b1[nf], B1s + ro + co);
                LDSM_X2(b3[nf], B3s + ro + co);
            }
#pragma unroll
            for (int mf = 0; mf < 2; mf++)
#pragma unroll
                for (int nf = 0; nf < 4; nf++) {
                    MMA_F16(acc1[mf][nf], a[mf], b1[nf]);
                    MMA_F16(acc3[mf][nf], a[mf], b3[nf]);
                }
        }
    }

    // epilogue: silu(t1)*t3 -> g_h (fp16)
#pragma unroll
    for (int mf = 0; mf < 2; mf++) {
        int r0 = wm * 32 + mf * 16 + (lane >> 2);
#pragma unroll
        for (int half = 0; half < 2; half++) {
            int rr = r0 + half * 8;
            if (m0 + rr < Me) {
                __half* hp = g_h + (size_t)(base + m0 + rr) * H_DIM;
#pragma unroll
                for (int nf = 0; nf < 4; nf++) {
                    int cc = n0 + wn * 32 + nf * 8 + (lane & 3) * 2;
                    float z0 = acc1[mf][nf][half * 2 + 0];
                    float z1 = acc1[mf][nf][half * 2 + 1];
                    float h0 = z0 / (1.f + __expf(-z0)) * acc3[mf][nf][half * 2 + 0];
                    float h1 = z1 / (1.f + __expf(-z1)) * acc3[mf][nf][half * 2 + 1];
                    uint32_t hv = pack_half2(h0, h1);
                    *reinterpret_cast<uint32_t*>(hp + cc) = hv;
                }
            }
        }
    }
}

// ================= GEMM2: y = h @ W2  (tile 128x256, fp16, 3-stage) =================
#define G2_STAGE 49152
#define G2_SMEM  (3 * G2_STAGE)
__global__ __launch_bounds__(512, 1) void gemm2_wide() {
    const int NT = H_DIM / 64;      // 32 k-tiles
    int e  = blockIdx.y;
    int Me = g_cnt[e];
    int m0 = blockIdx.x * 128;
    if (m0 >= Me) return;
    int n0   = blockIdx.z * 256;
    int base = g_off[e];
    const __half* Bm = g_w2T + (size_t)e * D_DIM * H_DIM;

    extern __shared__ char ds[];
    uint32_t sb = smem_u32(ds);
    int tid = threadIdx.x, lane = tid & 31, wid = tid >> 5;
    int wm = wid & 3, wn = wid >> 2;

    // A: 128 rows x 8 chunks -> 2/thread; B: 256 rows x 8 chunks -> 4/thread
    const __half* aSrc[2]; uint32_t aDst[2];
#pragma unroll
    for (int j = 0; j < 2; j++) {
        int v = tid + j * 512, q = v & 7, m = v >> 3;
        int mg = m0 + m; if (mg > Me - 1) mg = Me - 1;
        aSrc[j] = g_h + (size_t)(base + mg) * H_DIM + q * 8;
        aDst[j] = sb + (uint32_t)(m * 128) + (uint32_t)((q ^ (m & 7)) << 4);
    }
    const __half* bSrc[4]; uint32_t bDst[4];
#pragma unroll
    for (int j = 0; j < 4; j++) {
        int v = tid + j * 512, q = v & 7, n = v >> 3;
        bSrc[j] = Bm + (size_t)(n0 + n) * H_DIM + q * 8;
        bDst[j] = sb + 16384u + (uint32_t)(n * 128) + (uint32_t)((q ^ (n & 7)) << 4);
    }

    float acc[2][8][4];
#pragma unroll
    for (int mf = 0; mf < 2; mf++)
#pragma unroll
        for (int nf = 0; nf < 8; nf++)
#pragma unroll
            for (int r = 0; r < 4; r++) acc[mf][nf][r] = 0.f;

#pragma unroll
    for (int s = 0; s < 2; s++) {
        uint32_t bo = (uint32_t)s * G2_STAGE;
        int kof = s * 64;
#pragma unroll
        for (int j = 0; j < 2; j++) CP_ASYNC16(aDst[j] + bo, aSrc[j] + kof);
#pragma unroll
        for (int j = 0; j < 4; j++) CP_ASYNC16(bDst[j] + bo, bSrc[j] + kof);
        CP_COMMIT();
    }

    int arow[2];
#pragma unroll
    for (int mf = 0; mf < 2; mf++)
        arow[mf] = wm * 32 + mf * 16 + (lane & 15);
    int aci = lane >> 4;
    int brow[8];
#pragma unroll
    for (int nf = 0; nf < 8; nf++)
        brow[nf] = wn * 64 + nf * 8 + (lane & 7);
    int bci = (lane >> 3) & 1;

    int bufc = 0, bufl = 2;
    for (int t = 0; t < NT; t++) {
        CP_WAIT1();
        __syncthreads();
        int ls = t + 2;
        if (ls < NT) {
            uint32_t bo = (uint32_t)bufl * G2_STAGE;
            int kof = ls * 64;
#pragma unroll
            for (int j = 0; j < 2; j++) CP_ASYNC16(aDst[j] + bo, aSrc[j] + kof);
#pragma unroll
            for (int j = 0; j < 4; j++) CP_ASYNC16(bDst[j] + bo, bSrc[j] + kof);
        }
        CP_COMMIT();
        if (++bufl == 3) bufl = 0;

        uint32_t As = sb + (uint32_t)bufc * G2_STAGE;
        uint32_t Bs = As + 16384u;
        if (++bufc == 3) bufc = 0;
#pragma unroll
        for (int ks = 0; ks < 4; ks++) {
            uint32_t a[2][4];
#pragma unroll
            for (int mf = 0; mf < 2; mf++) {
                uint32_t ad = As + (uint32_t)(arow[mf] * 128)
                            + (uint32_t)((((2 * ks + aci) ^ (arow[mf] & 7))) << 4);
                LDSM_X4(a[mf], ad);
            }
            uint32_t b[8][2];
#pragma unroll
            for (int nf = 0; nf < 8; nf++) {
                uint32_t bd = Bs + (uint32_t)(brow[nf] * 128)
                            + (uint32_t)((((2 * ks + bci) ^ (brow[nf] & 7))) << 4);
                LDSM_X2(b[nf], bd);
            }
#pragma unroll
            for (int mf = 0; mf < 2; mf++)
#pragma unroll
                for (int nf = 0; nf < 8; nf++)
                    MMA_F16(acc[mf][nf], a[mf], b[nf]);
        }
    }

#pragma unroll
    for (int mf = 0; mf < 2; mf++) {
        int r0 = wm * 32 + mf * 16 + (lane >> 2);
#pragma unroll
        for (int half = 0; half < 2; half++) {
            int rr = r0 + half * 8;
            if (m0 + rr < Me) {
                size_t rowoff = (size_t)(base + m0 + rr) * D_DIM;
#pragma unroll
                for (int nf = 0; nf < 8; nf++) {
                    int cc = n0 + wn * 64 + nf * 8 + (lane & 3) * 2;
                    float2 v = make_float2(acc[mf][nf][half * 2 + 0],
                                           acc[mf][nf][half * 2 + 1]);
                    *reinterpret_cast<float2*>(g_y + rowoff + cc) = v;
                }
            }
        }
    }
}

// ---------------- combine: out[t] = p0*y[pos0] + p1*y[pos1] ----------------
__global__ void combine_kernel(float* __restrict__ out) {
    int t = blockIdx.x;
    float p0 = g_prob[2 * t], p1 = g_prob[2 * t + 1];
    int   q0 = g_tokpos[2 * t], q1 = g_tokpos[2 * t + 1];
    int i = threadIdx.x * 4;
    float4 a = *reinterpret_cast<const float4*>(g_y + (size_t)q0 * D_DIM + i);
    float4 b = *reinterpret_cast<const float4*>(g_y + (size_t)q1 * D_DIM + i);
    float4 o;
    o.x = p0 * a.x + p1 * b.x;
    o.y = p0 * a.y + p1 * b.y;
    o.z = p0 * a.z + p1 * b.z;
    o.w = p0 * a.w + p1 * b.w;
    *reinterpret_cast<float4*>(out + (size_t)t * D_DIM + i) = o;
}

// ---------------- launch ----------------
extern "C" void kernel_launch(void* const* d_in, const int* in_sizes, int n_in,
                              void* d_out, int out_size) {
    const float* x  = (const float*)d_in[0];   // (B,S,D)
    const float* wg = (const float*)d_in[1];   // (D,E)
    const float* w1 = (const float*)d_in[2];   // (E,D,H)
    const float* w3 = (const float*)d_in[3];   // (E,D,H)
    const float* w2 = (const float*)d_in[4];   // (E,H,D)
    float* out = (float*)d_out;
    (void)in_sizes; (void)n_in; (void)out_size;

    cudaFuncSetAttribute(gemm1_fused, cudaFuncAttributeMaxDynamicSharedMemorySize, G1_SMEM);
    cudaFuncSetAttribute(gemm2_wide,  cudaFuncAttributeMaxDynamicSharedMemorySize, G2_SMEM);

    void *p_w1T, *p_w3T, *p_w2T;
    cudaGetSymbolAddress(&p_w1T, g_w1T);
    cudaGetSymbolAddress(&p_w3T, g_w3T);
    cudaGetSymbolAddress(&p_w2T, g_w2T);

    init_kernel<<<1, 32>>>();
    cvt_x_kernel<<<(T_TOK * D_DIM / 8) / 256, 256>>>(x);

    dim3 tb(32, 8);
    transpose_cvt_kernel<<<dim3(H_DIM / 32, D_DIM / 32, E_NUM), tb>>>(w1, (__half*)p_w1T, D_DIM, H_DIM);
    transpose_cvt_kernel<<<dim3(H_DIM / 32, D_DIM / 32, E_NUM), tb>>>(w3, (__half*)p_w3T, D_DIM, H_DIM);
    transpose_cvt_kernel<<<dim3(D_DIM / 32, H_DIM / 32, E_NUM), tb>>>(w2, (__half*)p_w2T, H_DIM, D_DIM);

    gate_kernel<<<(T_TOK * 32 + 255) / 256, 256>>>(x, wg);
    offsets_kernel<<<1, 32>>>();
    scatter_kernel<<<(T_TOK + 255) / 256, 256>>>();

    dim3 g1(NA / 128, E_NUM, H_DIM / 128);   // (128, 8, 16)
    gemm1_fused<<<g1, 512, G1_SMEM>>>();

    dim3 g2(NA / 128, E_NUM, D_DIM / 256);   // (128, 8, 4)
    gemm2_wide<<<g2, 512, G2_SMEM>>>();

    combine_kernel<<<T_TOK, 256>>>(out);
}